// round 6
// baseline (speedup 1.0000x reference)
#include <cuda_runtime.h>
#include <math.h>

// Problem constants (fixed by the reference)
#define NN      64
#define GRID_N  (NN * NN * NN)   // 262144
#define NQ      200
#define BATCH   2
#define KPT     7                // ceil(NQ/32) charges per lane
#define MAXB    1024             // max blocks for scratch

// Scratch for cross-block reduction (allocation-free: __device__ globals)
__device__ float        g_partials[MAXB];
__device__ unsigned int g_ticket = 0;   // self-resetting via atomicInc wrap

__global__ __launch_bounds__(256)
void ibl_loss_kernel(const float* __restrict__ field,    // (BATCH,1,64,64,64)
                     const float* __restrict__ q,        // (NQ,)
                     const float* __restrict__ xq,       // (NQ,3)
                     const int*   __restrict__ xi,
                     const int*   __restrict__ yi,
                     const int*   __restrict__ zi,
                     const float* __restrict__ normals,  // (NB,3)
                     int nb,
                     float* __restrict__ out)
{
    __shared__ float4 sq[NQ];   // {xq.x, xq.y, xq.z, q}

    const float  EPSF   = 1.1920929e-07f;               // np.finfo(float32).eps
    const float  INV4PI = 1.0f / (4.0f * 3.14159265358979323846f);
    const double DXD    = 1.0 / 63.0;                   // reference DX (float64)
    const float  RDX    = 63.0f;                        // 1/DX in fp32

    const int tid  = threadIdx.x;
    const int lane = tid & 31;
    const int warp = tid >> 5;
    const int i    = blockIdx.x * 8 + warp;   // one warp per boundary point
    const bool leader = (lane == 0) && (i < nb);

    // ---- Issue index loads immediately (start the DRAM round-trip early)
    int x = 0, y = 0, z = 0;
    if (i < nb) { x = xi[i]; y = yi[i]; z = zi[i]; }

    // ---- Stage charges into shared (one per thread, 200 <= 256); overlaps idx loads
    if (tid < NQ) {
        sq[tid] = make_float4(xq[3 * tid + 0], xq[3 * tid + 1], xq[3 * tid + 2], q[tid]);
    }

    const int flat = (x * NN + y) * NN + z;

    // ---- Hoisted leader loads: normals + field stencil (both batches).
    float nx = 0.f, ny = 0.f, nz = 0.f;
    float c0[BATCH], lft[BATCH], rgt[BATCH], bel[BATCH], abv[BATCH], bck[BATCH], frt[BATCH];
    if (leader) {
        nx = normals[3 * i + 0];
        ny = normals[3 * i + 1];
        nz = normals[3 * i + 2];
        #pragma unroll
        for (int b = 0; b < BATCH; b++) {
            const float* __restrict__ o = field + b * GRID_N;
            c0[b]  = o[flat];
            lft[b] = o[flat - NN * NN];
            rgt[b] = o[flat + NN * NN];
            bel[b] = o[flat - NN];
            abv[b] = o[flat + NN];
            bck[b] = o[flat - 1];
            frt[b] = o[flat + 1];
        }
    } else {
        #pragma unroll
        for (int b = 0; b < BATCH; b++) {
            c0[b] = lft[b] = rgt[b] = bel[b] = abv[b] = bck[b] = frt[b] = 0.f;
        }
    }

    // ---- Grid-point coords: bit-exact replica of reference's fp64->fp32 points
    const float px = (float)((double)x * DXD);
    const float py = (float)((double)y * DXD);
    const float pz = (float)((double)z * DXD);

    __syncthreads();   // sq ready

    // ---- Green's function partial sums: lane handles charges lane, lane+32, ...
    float g = 0.0f, gx = 0.0f, gy = 0.0f, gz = 0.0f;
    if (i < nb) {
        #pragma unroll
        for (int kk = 0; kk < KPT; kk++) {
            const int k = lane + kk * 32;
            if (k < NQ) {
                const float4 ch = sq[k];
                const float dx = px - ch.x;
                const float dy = py - ch.y;
                const float dz = pz - ch.z;
                const float r2 = fmaf(dx, dx, fmaf(dy, dy, dz * dz));
                const float inv_r  = (r2 > 0.0f) ? rsqrtf(r2) : (1.0f / EPSF);
                g = fmaf(ch.w, inv_r, g);
                const float inv_r3 = inv_r * inv_r * inv_r;
                const float coef   = -ch.w * inv_r3;
                gx = fmaf(coef, dx, gx);
                gy = fmaf(coef, dy, gy);
                gz = fmaf(coef, dz, gz);
            }
        }
    }

    // ---- Reduce 4 accumulators across the warp
    #pragma unroll
    for (int off = 16; off > 0; off >>= 1) {
        g  += __shfl_down_sync(0xffffffffu, g,  off);
        gx += __shfl_down_sync(0xffffffffu, gx, off);
        gy += __shfl_down_sync(0xffffffffu, gy, off);
        gz += __shfl_down_sync(0xffffffffu, gz, off);
    }

    float local = 0.0f;
    if (leader) {
        g  *= INV4PI;
        gx *= INV4PI;
        gy *= INV4PI;
        gz *= INV4PI;

        const float gcnd = gx * nx + gy * ny + gz * nz;

        // loss1: (mol_b - out_b)^2 == g^2, identical for both batches
        local = (float)BATCH * (g * g);

        // loss2: one-sided normal derivatives per batch (preloaded stencil)
        #pragma unroll
        for (int b = 0; b < BATCH; b++) {
            const float dmx = (c0[b]  - lft[b]) * RDX;
            const float dpx = (rgt[b] - c0[b])  * RDX;
            const float dmy = (c0[b]  - bel[b]) * RDX;
            const float dpy = (abv[b] - c0[b])  * RDX;
            const float dmz = (c0[b]  - bck[b]) * RDX;
            const float dpz = (frt[b] - c0[b])  * RDX;

            const float gx_in  = (nx > 0.0f) ? dmx : dpx;
            const float gx_out = (nx > 0.0f) ? dpx : dmx;
            const float gy_in  = (ny > 0.0f) ? dmy : dpy;
            const float gy_out = (ny > 0.0f) ? dpy : dmy;
            const float gz_in  = (nz > 0.0f) ? dmz : dpz;
            const float gz_out = (nz > 0.0f) ? dpz : dmz;

            const float nd_in  = gx_in  * nx + gy_in  * ny + gz_in  * nz;
            const float nd_out = gx_out * nx + gy_out * ny + gz_out * nz;

            // E_IN = 1, E_OUT = 80
            const float t = (nd_in + gcnd) - 80.0f * nd_out;
            local = fmaf(t, t, local);
        }
    }

    // ---- Block reduction: leaders (lane 0 of each warp) -> warp 0
    __shared__ float wsum[8];
    if (lane == 0) wsum[warp] = local;
    __syncthreads();

    float v = 0.0f;
    if (warp == 0) {
        v = (lane < 8) ? wsum[lane] : 0.0f;
        #pragma unroll
        for (int off = 4; off > 0; off >>= 1)
            v += __shfl_down_sync(0xffffffffu, v, off);
    }

    // ---- Cross-block: last block reduces all partials (self-resetting ticket)
    const int nblocks = gridDim.x;
    __shared__ bool s_is_last;
    if (tid == 0) {
        g_partials[blockIdx.x] = v;
        __threadfence();
        unsigned int t = atomicInc(&g_ticket, (unsigned int)(nblocks - 1));
        s_is_last = (t == (unsigned int)(nblocks - 1));
    }
    __syncthreads();

    if (s_is_last && warp == 0) {
        const volatile float* vp = g_partials;
        float s = 0.0f;
        for (int j = lane; j < nblocks; j += 32)
            s += vp[j];
        #pragma unroll
        for (int off = 16; off > 0; off >>= 1)
            s += __shfl_down_sync(0xffffffffu, s, off);
        if (lane == 0) {
            const float inv_den = 1.0f / (float)(BATCH * nb);
            out[0] = s * inv_den;
        }
    }
}

extern "C" void kernel_launch(void* const* d_in, const int* in_sizes, int n_in,
                              void* d_out, int out_size)
{
    const float* field   = (const float*)d_in[0];  // output (2,1,64,64,64)
    const float* q       = (const float*)d_in[1];  // (200,)
    const float* xq      = (const float*)d_in[2];  // (200,3)
    // d_in[3] = points (no longer needed; recomputed on device bit-exactly)
    const int*   xi      = (const int*)  d_in[4];
    const int*   yi      = (const int*)  d_in[5];
    const int*   zi      = (const int*)  d_in[6];
    const float* normals = (const float*)d_in[7];  // (NB,3)
    float*       out     = (float*)d_out;

    const int nb = in_sizes[4];

    const int threads = 256;                 // 8 warps = 8 boundary points / block
    int blocks = (nb + 7) / 8;
    if (blocks > MAXB) blocks = MAXB;        // nb ~ 4.5K -> ~560 blocks, fits

    ibl_loss_kernel<<<blocks, threads>>>(field, q, xq,
                                         xi, yi, zi, normals, nb, out);
}

// round 7
// speedup vs baseline: 1.1553x; 1.1553x over previous
#include <cuda_runtime.h>
#include <math.h>

// Problem constants (fixed by the reference)
#define NN      64
#define GRID_N  (NN * NN * NN)   // 262144
#define NQ      200
#define BATCH   2
#define CH      8                // threads cooperating per boundary point
#define QPT     (NQ / CH)        // 25 charges per thread
#define TPB     512              // threads per block
#define PPB     (TPB / CH)       // 64 boundary points per block

// Scratch for cross-block reduction (allocation-free: __device__ globals)
__device__ float        g_accum  = 0.0f;  // reset by last block each launch
__device__ unsigned int g_ticket = 0;     // self-resetting via atomicInc wrap

__global__ __launch_bounds__(TPB)
void ibl_loss_kernel(const float* __restrict__ field,    // (BATCH,1,64,64,64)
                     const float* __restrict__ q,        // (NQ,)
                     const float* __restrict__ xq,       // (NQ,3)
                     const int*   __restrict__ xi,
                     const int*   __restrict__ yi,
                     const int*   __restrict__ zi,
                     const float* __restrict__ normals,  // (NB,3)
                     int nb,
                     float* __restrict__ out)
{
    __shared__ float4 sq[NQ];   // {xq.x, xq.y, xq.z, q}

    const float  EPSF   = 1.1920929e-07f;               // np.finfo(float32).eps
    const float  INV4PI = 1.0f / (4.0f * 3.14159265358979323846f);
    const double DXD    = 1.0 / 63.0;                   // reference DX (float64)
    const float  RDX    = 63.0f;                        // 1/DX in fp32

    const int tid  = threadIdx.x;
    const int gtid = blockIdx.x * TPB + tid;
    const int i    = gtid >> 3;        // boundary point index
    const int c    = gtid & (CH - 1);  // charge-chunk index within point
    const bool leader = (c == 0) && (i < nb);

    // ---- Issue index loads immediately (start the memory round-trip early)
    int x = 0, y = 0, z = 0;
    if (i < nb) { x = __ldg(xi + i); y = __ldg(yi + i); z = __ldg(zi + i); }

    // ---- Stage charges into shared (one per thread, 200 <= 512)
    if (tid < NQ) {
        sq[tid] = make_float4(__ldg(xq + 3 * tid + 0),
                              __ldg(xq + 3 * tid + 1),
                              __ldg(xq + 3 * tid + 2),
                              __ldg(q + tid));
    }

    const int flat = (x * NN + y) * NN + z;

    // ---- Hoisted leader loads: normals + field stencil (both batches)
    float nx = 0.f, ny = 0.f, nz = 0.f;
    float c0[BATCH], lft[BATCH], rgt[BATCH], bel[BATCH], abv[BATCH], bck[BATCH], frt[BATCH];
    if (leader) {
        nx = normals[3 * i + 0];
        ny = normals[3 * i + 1];
        nz = normals[3 * i + 2];
        #pragma unroll
        for (int b = 0; b < BATCH; b++) {
            const float* __restrict__ o = field + b * GRID_N;
            c0[b]  = o[flat];
            lft[b] = o[flat - NN * NN];
            rgt[b] = o[flat + NN * NN];
            bel[b] = o[flat - NN];
            abv[b] = o[flat + NN];
            bck[b] = o[flat - 1];
            frt[b] = o[flat + 1];
        }
    } else {
        #pragma unroll
        for (int b = 0; b < BATCH; b++) {
            c0[b] = lft[b] = rgt[b] = bel[b] = abv[b] = bck[b] = frt[b] = 0.f;
        }
    }

    // ---- Grid-point coords: bit-exact replica of reference's fp64->fp32 points
    const float px = (float)((double)x * DXD);
    const float py = (float)((double)y * DXD);
    const float pz = (float)((double)z * DXD);

    __syncthreads();   // sq ready

    // ---- Green's function partial sums over this thread's 25 charges
    float g = 0.0f, gx = 0.0f, gy = 0.0f, gz = 0.0f;
    if (i < nb) {
        const int k0 = c * QPT;
        #pragma unroll
        for (int kk = 0; kk < QPT; kk++) {
            const float4 ch = sq[k0 + kk];
            const float dx = px - ch.x;
            const float dy = py - ch.y;
            const float dz = pz - ch.z;
            const float r2 = fmaf(dx, dx, fmaf(dy, dy, dz * dz));
            const float inv_r  = (r2 > 0.0f) ? rsqrtf(r2) : (1.0f / EPSF);
            g = fmaf(ch.w, inv_r, g);
            const float inv_r3 = inv_r * inv_r * inv_r;
            const float coef   = -ch.w * inv_r3;
            gx = fmaf(coef, dx, gx);
            gy = fmaf(coef, dy, gy);
            gz = fmaf(coef, dz, gz);
        }
    }

    // ---- Reduce 4 accumulators across the 8-thread group
    #pragma unroll
    for (int off = CH / 2; off > 0; off >>= 1) {
        g  += __shfl_down_sync(0xffffffffu, g,  off, CH);
        gx += __shfl_down_sync(0xffffffffu, gx, off, CH);
        gy += __shfl_down_sync(0xffffffffu, gy, off, CH);
        gz += __shfl_down_sync(0xffffffffu, gz, off, CH);
    }

    float local = 0.0f;
    if (leader) {
        g  *= INV4PI;
        gx *= INV4PI;
        gy *= INV4PI;
        gz *= INV4PI;

        const float gcnd = gx * nx + gy * ny + gz * nz;

        // loss1: (mol_b - out_b)^2 == g^2, identical for both batches
        local = (float)BATCH * (g * g);

        // loss2: one-sided normal derivatives per batch (preloaded stencil)
        #pragma unroll
        for (int b = 0; b < BATCH; b++) {
            const float dmx = (c0[b]  - lft[b]) * RDX;
            const float dpx = (rgt[b] - c0[b])  * RDX;
            const float dmy = (c0[b]  - bel[b]) * RDX;
            const float dpy = (abv[b] - c0[b])  * RDX;
            const float dmz = (c0[b]  - bck[b]) * RDX;
            const float dpz = (frt[b] - c0[b])  * RDX;

            const float gx_in  = (nx > 0.0f) ? dmx : dpx;
            const float gx_out = (nx > 0.0f) ? dpx : dmx;
            const float gy_in  = (ny > 0.0f) ? dmy : dpy;
            const float gy_out = (ny > 0.0f) ? dpy : dmy;
            const float gz_in  = (nz > 0.0f) ? dmz : dpz;
            const float gz_out = (nz > 0.0f) ? dpz : dmz;

            const float nd_in  = gx_in  * nx + gy_in  * ny + gz_in  * nz;
            const float nd_out = gx_out * nx + gy_out * ny + gz_out * nz;

            // E_IN = 1, E_OUT = 80
            const float t = (nd_in + gcnd) - 80.0f * nd_out;
            local = fmaf(t, t, local);
        }
    }

    // ---- Block reduction: full-warp shuffle (only group leaders hold nonzero)
    float v = local;
    #pragma unroll
    for (int off = 16; off > 0; off >>= 1)
        v += __shfl_down_sync(0xffffffffu, v, off);

    __shared__ float wsum[TPB / 32];
    const int warp = tid >> 5;
    const int lane = tid & 31;
    if (lane == 0) wsum[warp] = v;
    __syncthreads();

    if (warp == 0) {
        v = (lane < (TPB / 32)) ? wsum[lane] : 0.0f;
        #pragma unroll
        for (int off = (TPB / 64); off > 0; off >>= 1)
            v += __shfl_down_sync(0xffffffffu, v, off);
    }

    // ---- Cross-block: atomic accumulate, last block writes + resets
    const int nblocks = gridDim.x;
    __shared__ bool s_is_last;
    if (tid == 0) {
        atomicAdd(&g_accum, v);
        __threadfence();
        unsigned int t = atomicInc(&g_ticket, (unsigned int)(nblocks - 1));
        s_is_last = (t == (unsigned int)(nblocks - 1));
    }
    __syncthreads();

    if (s_is_last && tid == 0) {
        volatile float* ap = &g_accum;
        const float s = *ap;
        const float inv_den = 1.0f / (float)(BATCH * nb);
        out[0] = s * inv_den;
        *ap = 0.0f;          // reset for next graph replay
        __threadfence();
    }
}

extern "C" void kernel_launch(void* const* d_in, const int* in_sizes, int n_in,
                              void* d_out, int out_size)
{
    const float* field   = (const float*)d_in[0];  // output (2,1,64,64,64)
    const float* q       = (const float*)d_in[1];  // (200,)
    const float* xq      = (const float*)d_in[2];  // (200,3)
    // d_in[3] = points (recomputed on device bit-exactly)
    const int*   xi      = (const int*)  d_in[4];
    const int*   yi      = (const int*)  d_in[5];
    const int*   zi      = (const int*)  d_in[6];
    const float* normals = (const float*)d_in[7];  // (NB,3)
    float*       out     = (float*)d_out;

    const int nb = in_sizes[4];

    const int blocks = (nb + PPB - 1) / PPB;   // ~71 blocks for nb ~ 4.5K

    ibl_loss_kernel<<<blocks, TPB>>>(field, q, xq,
                                     xi, yi, zi, normals, nb, out);
}